// round 7
// baseline (speedup 1.0000x reference)
#include <cuda_runtime.h>
#include <cuda_bf16.h>
#include <cstdint>

#define NN 16384
#define DD 64
#define BLK 128           // CTA tile is BLK x BLK
#define NTILES (NN / BLK) // 128
#define NPAIRS (NTILES * (NTILES + 1) / 2)   // 8256 upper-tri tiles
#define PREP_BLOCKS 256

// ---------------- device scratch (no allocations allowed) ----------------
__device__ float  g_part[NPAIRS];          // per-CTA Q partials (overwritten)
__device__ float  g_pSa[PREP_BLOCKS], g_pSxi[PREP_BLOCKS], g_pSy[PREP_BLOCKS];
__device__ float  g_w[NN];
__device__ __align__(128) __nv_bfloat16 g_hi[NN * DD];
__device__ __align__(128) __nv_bfloat16 g_lo[NN * DD];

// ---------------- helpers ----------------
__device__ __forceinline__ uint32_t smem_u32(const void* p) {
    uint32_t a;
    asm("{ .reg .u64 t; cvta.to.shared.u64 t, %1; cvt.u32.u64 %0, t; }"
        : "=r"(a) : "l"(p));
    return a;
}

#define CP_ASYNC16(dst, src) \
    asm volatile("cp.async.cg.shared.global [%0], [%1], 16;" \
                 :: "r"(dst), "l"(src) : "memory")
#define CP_COMMIT() asm volatile("cp.async.commit_group;" ::: "memory")
#define CP_WAIT0()  asm volatile("cp.async.wait_group 0;" ::: "memory")

__device__ __forceinline__ void ldsm_x4(uint32_t& r0, uint32_t& r1,
                                        uint32_t& r2, uint32_t& r3, uint32_t addr) {
    asm volatile("ldmatrix.sync.aligned.m8n8.x4.shared.b16 {%0,%1,%2,%3}, [%4];"
                 : "=r"(r0), "=r"(r1), "=r"(r2), "=r"(r3) : "r"(addr));
}

__device__ __forceinline__ void mma_16816(float* c, const uint32_t* a, const uint32_t* b) {
    asm volatile(
        "mma.sync.aligned.m16n8k16.row.col.f32.bf16.bf16.f32 "
        "{%0,%1,%2,%3}, {%4,%5,%6,%7}, {%8,%9}, {%0,%1,%2,%3};"
        : "+f"(c[0]), "+f"(c[1]), "+f"(c[2]), "+f"(c[3])
        : "r"(a[0]), "r"(a[1]), "r"(a[2]), "r"(a[3]), "r"(b[0]), "r"(b[1]));
}

// scalars may be int32 or float32 bit patterns
__device__ __forceinline__ float scal_as_float(const int* p) {
    int v = *p;
    if (v < 0 || v >= 0x00800000) return __int_as_float(v);
    return (float)v;
}
__device__ __forceinline__ int scal_as_int(const int* p) {
    int v = *p;
    if (v < 0 || v >= 0x00800000) return (int)(__int_as_float(v) + 0.5f);
    return v;
}

// ---------------- prep: relu sums + w + bf16 hi/lo split of x ----------------
__global__ __launch_bounds__(256)
void svm_prep_kernel(const float* __restrict__ x,
                     const float* __restrict__ alpha,
                     const float* __restrict__ xi,
                     const float* __restrict__ y) {
    int i = blockIdx.x * blockDim.x + threadIdx.x;
    for (int e = i; e < NN * DD; e += gridDim.x * blockDim.x) {
        float v = x[e];
        __nv_bfloat16 h = __float2bfloat16_rn(v);
        g_hi[e] = h;
        g_lo[e] = __float2bfloat16_rn(v - __bfloat162float(h));
    }
    float a = 0.f, xr = 0.f, yv = 0.f;
    if (i < NN) {
        a  = fmaxf(alpha[i], 0.f);
        xr = fmaxf(xi[i], 0.f);
        yv = y[i];
        g_w[i] = a * yv;
    }
    #pragma unroll
    for (int o = 16; o > 0; o >>= 1) {
        a  += __shfl_down_sync(0xffffffffu, a,  o);
        xr += __shfl_down_sync(0xffffffffu, xr, o);
        yv += __shfl_down_sync(0xffffffffu, yv, o);
    }
    __shared__ float rA[8], rX[8], rY[8];
    int wid = threadIdx.x >> 5, lid = threadIdx.x & 31;
    if (lid == 0) { rA[wid] = a; rX[wid] = xr; rY[wid] = yv; }
    __syncthreads();
    if (threadIdx.x == 0) {
        float sa = 0.f, sx = 0.f, sy = 0.f;
        #pragma unroll
        for (int w = 0; w < 8; ++w) { sa += rA[w]; sx += rX[w]; sy += rY[w]; }
        g_pSa[blockIdx.x]  = sa;
        g_pSxi[blockIdx.x] = sx;
        g_pSy[blockIdx.x]  = sy;
    }
}

// ---------------- main Gram-tile kernel (upper-tri, mma.sync bf16) ----------------
// smem tiles: 128 rows x 64 bf16 (128B/row), SW128 chunk swizzle:
//   byte off = row*128 + ((c16 ^ (row&7)) * 16)
#define T_AHI 0
#define T_ALO 16384
#define T_BHI 32768
#define T_BLO 49152
#define OFF_WJ 65536
#define OFF_YI 66048
#define OFF_WI 66560
#define OFF_YJ 67072
#define SMEM_BYTES (67584 + 256)

__global__ __launch_bounds__(256, 2)
void svm_quad_mma_kernel(const float* __restrict__ y,
                         const int* __restrict__ coeff_p,
                         const int* __restrict__ degree_p) {
    extern __shared__ char smem_raw[];
    const uint32_t raw = smem_u32(smem_raw);
    const uint32_t base = (raw + 127u) & ~127u;
    char* smem = smem_raw + (base - raw);

    const int tid = threadIdx.x;
    const int wid = tid >> 5;
    const int lid = tid & 31;
    const int wm  = wid & 3;   // 4 warps along M
    const int wn  = wid >> 2;  // 2 warps along N

    // ---- triangular decode: blockIdx.x -> (I, J), I <= J ----
    int idx = blockIdx.x;
    int I = (int)((2.0 * NTILES + 1.0
                   - sqrt((2.0 * NTILES + 1.0) * (2.0 * NTILES + 1.0) - 8.0 * idx)) * 0.5);
    if (I > NTILES - 1) I = NTILES - 1;
    if (I < 0) I = 0;
    #pragma unroll 1
    while (I > 0 && (I * NTILES - (I * (I - 1)) / 2) > idx) --I;
    #pragma unroll 1
    while (((I + 1) * NTILES - ((I + 1) * I) / 2) <= idx) ++I;
    const int J = I + (idx - (I * NTILES - (I * (I - 1)) / 2));
    const int bi = I * BLK;
    const int bj = J * BLK;
    const bool offdiag = (I != J);

    // ---- async tile loads (4 x 1024 x 16B chunks, swizzled) ----
    {
        const char* sAhi = (const char*)(g_hi + (size_t)bi * DD);
        const char* sAlo = (const char*)(g_lo + (size_t)bi * DD);
        const char* sBhi = (const char*)(g_hi + (size_t)bj * DD);
        const char* sBlo = (const char*)(g_lo + (size_t)bj * DD);
        #pragma unroll
        for (int it = 0; it < 4; ++it) {
            int i = tid + it * 256;        // 0..1023 = row*8 + c16
            int row = i >> 3, c16 = i & 7;
            int sw = row * 128 + ((c16 ^ (row & 7)) << 4);
            int lin = i * 16;
            CP_ASYNC16(base + T_AHI + sw, sAhi + lin);
            CP_ASYNC16(base + T_ALO + sw, sAlo + lin);
            CP_ASYNC16(base + T_BHI + sw, sBhi + lin);
            CP_ASYNC16(base + T_BLO + sw, sBlo + lin);
        }
        CP_COMMIT();
        if (tid < 128) {
            *(float*)(smem + OFF_WJ + tid * 4) = g_w[bj + tid];
            *(float*)(smem + OFF_YI + tid * 4) = y[bi + tid];
            *(float*)(smem + OFF_WI + tid * 4) = g_w[bi + tid];
            *(float*)(smem + OFF_YJ + tid * 4) = y[bj + tid];
        }
        CP_WAIT0();
    }
    __syncthreads();

    // ---- per-lane ldmatrix address components ----
    const int q   = lid >> 3;   // matrix index 0..3
    const int seg = lid & 7;    // row within matrix
    const int rowA0 = wm * 32 + seg + ((q & 1) << 3);
    const int chA   = q >> 1;
    const int rowB0 = wn * 64 + seg + ((q >> 1) << 3);
    const int chB   = q & 1;

    float acc[2][8][4];
    #pragma unroll
    for (int am = 0; am < 2; ++am)
        #pragma unroll
        for (int bn = 0; bn < 8; ++bn)
            #pragma unroll
            for (int r = 0; r < 4; ++r) acc[am][bn][r] = 0.f;

    const uint32_t aBases[3] = { base + T_AHI, base + T_AHI, base + T_ALO };
    const uint32_t bBases[3] = { base + T_BHI, base + T_BLO, base + T_BHI };

    #pragma unroll
    for (int pass = 0; pass < 3; ++pass) {
        const uint32_t aB = aBases[pass];
        const uint32_t bB = bBases[pass];
        #pragma unroll
        for (int ks = 0; ks < 4; ++ks) {
            uint32_t af[2][4];
            #pragma unroll
            for (int am = 0; am < 2; ++am) {
                int row = rowA0 + am * 16;
                int ch  = (chA + 2 * ks) ^ (row & 7);
                ldsm_x4(af[am][0], af[am][1], af[am][2], af[am][3],
                        aB + row * 128 + (ch << 4));
            }
            uint32_t bf[8][2];
            #pragma unroll
            for (int bn2 = 0; bn2 < 4; ++bn2) {
                int row = rowB0 + bn2 * 16;
                int ch  = (chB + 2 * ks) ^ (row & 7);
                ldsm_x4(bf[bn2 * 2][0], bf[bn2 * 2][1],
                        bf[bn2 * 2 + 1][0], bf[bn2 * 2 + 1][1],
                        bB + row * 128 + (ch << 4));
            }
            #pragma unroll
            for (int am = 0; am < 2; ++am)
                #pragma unroll
                for (int bn = 0; bn < 8; ++bn)
                    mma_16816(acc[am][bn], af[am], bf[bn]);
        }
    }

    // ---- epilogue: k = (v+coeff)^deg; off-diag tiles count both triangles ----
    const float coeff = scal_as_float(coeff_p);
    const int   deg   = scal_as_int(degree_p);
    const float* s_wJ = (const float*)(smem + OFF_WJ);
    const float* s_yI = (const float*)(smem + OFF_YI);
    const float* s_wI = (const float*)(smem + OFF_WI);
    const float* s_yJ = (const float*)(smem + OFF_YJ);

    const int rBase = wm * 32 + (lid >> 2);
    const int cBase = wn * 64 + 2 * (lid & 3);

    float part = 0.f;
    #pragma unroll
    for (int am = 0; am < 2; ++am) {
        const int r0i = rBase + am * 16;
        const float yr0 = s_yI[r0i],     yr1 = s_yI[r0i + 8];
        const float wr0 = s_wI[r0i],     wr1 = s_wI[r0i + 8];
        float s0w = 0.f, s1w = 0.f;
        float s0y = 0.f, s1y = 0.f;
        #pragma unroll
        for (int bn = 0; bn < 8; ++bn) {
            const int c0i = cBase + bn * 8;
            const float wc0 = s_wJ[c0i], wc1 = s_wJ[c0i + 1];
            const float yc0 = s_yJ[c0i], yc1 = s_yJ[c0i + 1];
            float k0, k1, k2, k3;
            if (deg == 3) {
                float v0 = acc[am][bn][0] + coeff;
                float v1 = acc[am][bn][1] + coeff;
                float v2 = acc[am][bn][2] + coeff;
                float v3 = acc[am][bn][3] + coeff;
                k0 = v0 * v0 * v0; k1 = v1 * v1 * v1;
                k2 = v2 * v2 * v2; k3 = v3 * v3 * v3;
            } else {
                float v[4], kk[4];
                #pragma unroll
                for (int r = 0; r < 4; ++r) {
                    v[r] = acc[am][bn][r] + coeff;
                    float p = 1.f;
                    for (int d = 0; d < deg; ++d) p *= v[r];
                    kk[r] = p;
                }
                k0 = kk[0]; k1 = kk[1]; k2 = kk[2]; k3 = kk[3];
            }
            s0w = fmaf(wc0, k0, s0w); s0w = fmaf(wc1, k1, s0w);
            s1w = fmaf(wc0, k2, s1w); s1w = fmaf(wc1, k3, s1w);
            s0y = fmaf(yc0, k0, s0y); s0y = fmaf(yc1, k1, s0y);
            s1y = fmaf(yc0, k2, s1y); s1y = fmaf(yc1, k3, s1y);
        }
        part = fmaf(yr0, s0w, part);
        part = fmaf(yr1, s1w, part);
        if (offdiag) {
            part = fmaf(wr0, s0y, part);
            part = fmaf(wr1, s1y, part);
        }
    }

    // ---- block reduce -> per-CTA partial (no atomics) ----
    #pragma unroll
    for (int o = 16; o > 0; o >>= 1)
        part += __shfl_down_sync(0xffffffffu, part, o);
    __shared__ float red[8];
    if (lid == 0) red[wid] = part;
    __syncthreads();
    if (tid == 0) {
        float s = 0.f;
        #pragma unroll
        for (int w = 0; w < 8; ++w) s += red[w];
        g_part[blockIdx.x] = s;
    }
}

// ---------------- final reduction + loss ----------------
__global__ __launch_bounds__(256)
void svm_fin_kernel(const float* __restrict__ b,
                    const int*   __restrict__ C_p,
                    const int*   __restrict__ lambd_p,
                    float* __restrict__ out) {
    const int tid = threadIdx.x;
    double q = 0.0;
    for (int i = tid; i < NPAIRS; i += 256) q += (double)g_part[i];
    double sa = 0.0, sx = 0.0, sy = 0.0;
    if (tid < PREP_BLOCKS) {
        sa = (double)g_pSa[tid];
        sx = (double)g_pSxi[tid];
        sy = (double)g_pSy[tid];
    }
    // warp reduce doubles
    #pragma unroll
    for (int o = 16; o > 0; o >>= 1) {
        q  += __shfl_down_sync(0xffffffffu, q,  o);
        sa += __shfl_down_sync(0xffffffffu, sa, o);
        sx += __shfl_down_sync(0xffffffffu, sx, o);
        sy += __shfl_down_sync(0xffffffffu, sy, o);
    }
    __shared__ double rq[8], ra[8], rx[8], ry[8];
    int wid = tid >> 5, lid = tid & 31;
    if (lid == 0) { rq[wid] = q; ra[wid] = sa; rx[wid] = sx; ry[wid] = sy; }
    __syncthreads();
    if (tid == 0) {
        double Q = 0, Sa = 0, Sxi = 0, Sy = 0;
        #pragma unroll
        for (int w = 0; w < 8; ++w) {
            Q += rq[w]; Sa += ra[w]; Sxi += rx[w]; Sy += ry[w];
        }
        double C  = (double)scal_as_float(C_p);
        double la = (double)scal_as_float(lambd_p);
        double loss = 0.5 * Sa + C * Sxi
                    + la * ((Q + (double)b[0] * Sy + Sxi) / (double)NN - 1.0);
        out[0] = (float)loss;
    }
}

// ---------------- launch ----------------
extern "C" void kernel_launch(void* const* d_in, const int* in_sizes, int n_in,
                              void* d_out, int out_size) {
    const float* x      = (const float*)d_in[0];
    const float* y      = (const float*)d_in[1];
    const float* alpha  = (const float*)d_in[2];
    const float* xi     = (const float*)d_in[3];
    const float* b      = (const float*)d_in[4];
    const int*   coeff  = (const int*)d_in[5];
    const int*   degree = (const int*)d_in[6];
    const int*   Cc     = (const int*)d_in[7];
    const int*   lambd  = (const int*)d_in[8];
    float* out = (float*)d_out;

    static bool attr_set = false;
    if (!attr_set) {
        cudaFuncSetAttribute(svm_quad_mma_kernel,
                             cudaFuncAttributeMaxDynamicSharedMemorySize, SMEM_BYTES);
        attr_set = true;
    }

    svm_prep_kernel<<<PREP_BLOCKS, 256>>>(x, alpha, xi, y);
    svm_quad_mma_kernel<<<NPAIRS, 256, SMEM_BYTES>>>(y, coeff, degree);
    svm_fin_kernel<<<1, 256>>>(b, Cc, lambd, out);
}

// round 8
// speedup vs baseline: 1.0388x; 1.0388x over previous
#include <cuda_runtime.h>
#include <cuda_bf16.h>
#include <cuda_fp8.h>
#include <cstdint>

#define NN 16384
#define DD 64
#define BLK 128           // CTA tile is BLK x BLK
#define NTILES (NN / BLK) // 128
#define NPAIRS (NTILES * (NTILES + 1) / 2)   // 8256 upper-tri tiles
#define PREP_BLOCKS 512

// ---------------- device scratch (no allocations allowed) ----------------
__device__ float  g_part[NPAIRS];          // per-CTA Q partials (overwritten)
__device__ float  g_pSa[PREP_BLOCKS], g_pSxi[PREP_BLOCKS], g_pSy[PREP_BLOCKS];
__device__ float  g_w[NN];
__device__ __align__(128) __nv_bfloat16 g_hi[NN * DD];       // bf16 hi
__device__ __align__(128) uint8_t g_c1[NN * 128];            // [hi/16 | 16*lo] e4m3
__device__ __align__(128) uint8_t g_c2[NN * 128];            // [16*lo | hi/16] e4m3

// ---------------- helpers ----------------
__device__ __forceinline__ uint32_t smem_u32(const void* p) {
    uint32_t a;
    asm("{ .reg .u64 t; cvta.to.shared.u64 t, %1; cvt.u32.u64 %0, t; }"
        : "=r"(a) : "l"(p));
    return a;
}

#define CP_ASYNC16(dst, src) \
    asm volatile("cp.async.cg.shared.global [%0], [%1], 16;" \
                 :: "r"(dst), "l"(src) : "memory")
#define CP_COMMIT() asm volatile("cp.async.commit_group;" ::: "memory")
#define CP_WAIT0()  asm volatile("cp.async.wait_group 0;" ::: "memory")

__device__ __forceinline__ void ldsm_x4(uint32_t& r0, uint32_t& r1,
                                        uint32_t& r2, uint32_t& r3, uint32_t addr) {
    asm volatile("ldmatrix.sync.aligned.m8n8.x4.shared.b16 {%0,%1,%2,%3}, [%4];"
                 : "=r"(r0), "=r"(r1), "=r"(r2), "=r"(r3) : "r"(addr));
}

__device__ __forceinline__ void mma_16816(float* c, const uint32_t* a, const uint32_t* b) {
    asm volatile(
        "mma.sync.aligned.m16n8k16.row.col.f32.bf16.bf16.f32 "
        "{%0,%1,%2,%3}, {%4,%5,%6,%7}, {%8,%9}, {%0,%1,%2,%3};"
        : "+f"(c[0]), "+f"(c[1]), "+f"(c[2]), "+f"(c[3])
        : "r"(a[0]), "r"(a[1]), "r"(a[2]), "r"(a[3]), "r"(b[0]), "r"(b[1]));
}

__device__ __forceinline__ void mma_fp8(float* c, const uint32_t* a, const uint32_t* b) {
    asm volatile(
        "mma.sync.aligned.m16n8k32.row.col.f32.e4m3.e4m3.f32 "
        "{%0,%1,%2,%3}, {%4,%5,%6,%7}, {%8,%9}, {%0,%1,%2,%3};"
        : "+f"(c[0]), "+f"(c[1]), "+f"(c[2]), "+f"(c[3])
        : "r"(a[0]), "r"(a[1]), "r"(a[2]), "r"(a[3]), "r"(b[0]), "r"(b[1]));
}

// scalars may be int32 or float32 bit patterns
__device__ __forceinline__ float scal_as_float(const int* p) {
    int v = *p;
    if (v < 0 || v >= 0x00800000) return __int_as_float(v);
    return (float)v;
}
__device__ __forceinline__ int scal_as_int(const int* p) {
    int v = *p;
    if (v < 0 || v >= 0x00800000) return (int)(__int_as_float(v) + 0.5f);
    return v;
}

// ---------------- prep: relu sums + w + splits of x ----------------
__global__ __launch_bounds__(256)
void svm_prep_kernel(const float* __restrict__ x,
                     const float* __restrict__ alpha,
                     const float* __restrict__ xi,
                     const float* __restrict__ y) {
    int i = blockIdx.x * blockDim.x + threadIdx.x;
    for (int e = i; e < NN * DD; e += gridDim.x * blockDim.x) {
        float v = x[e];
        __nv_bfloat16 h = __float2bfloat16_rn(v);
        float hf = __bfloat162float(h);
        float lo = v - hf;
        g_hi[e] = h;
        int r = e >> 6;          // row
        int k = e & 63;          // col
        uint8_t h16 = (uint8_t)__nv_cvt_float_to_fp8(hf * 0.0625f, __NV_SATFINITE, __NV_E4M3);
        uint8_t l16 = (uint8_t)__nv_cvt_float_to_fp8(lo * 16.0f,   __NV_SATFINITE, __NV_E4M3);
        g_c1[r * 128 + k]      = h16;
        g_c1[r * 128 + 64 + k] = l16;
        g_c2[r * 128 + k]      = l16;
        g_c2[r * 128 + 64 + k] = h16;
    }
    float a = 0.f, xr = 0.f, yv = 0.f;
    if (i < NN) {
        a  = fmaxf(alpha[i], 0.f);
        xr = fmaxf(xi[i], 0.f);
        yv = y[i];
        g_w[i] = a * yv;
    }
    #pragma unroll
    for (int o = 16; o > 0; o >>= 1) {
        a  += __shfl_down_sync(0xffffffffu, a,  o);
        xr += __shfl_down_sync(0xffffffffu, xr, o);
        yv += __shfl_down_sync(0xffffffffu, yv, o);
    }
    __shared__ float rA[8], rX[8], rY[8];
    int wid = threadIdx.x >> 5, lid = threadIdx.x & 31;
    if (lid == 0) { rA[wid] = a; rX[wid] = xr; rY[wid] = yv; }
    __syncthreads();
    if (threadIdx.x == 0) {
        float sa = 0.f, sx = 0.f, sy = 0.f;
        #pragma unroll
        for (int w = 0; w < 8; ++w) { sa += rA[w]; sx += rX[w]; sy += rY[w]; }
        g_pSa[blockIdx.x]  = sa;
        g_pSxi[blockIdx.x] = sx;
        g_pSy[blockIdx.x]  = sy;
    }
}

// ---------------- main Gram-tile kernel ----------------
// smem tiles: 128 rows x 128B, XOR chunk swizzle:
//   byte off = row*128 + ((c16 ^ (row&7)) * 16)
#define T_HIA 0
#define T_HIB 16384
#define T_C1  32768
#define T_C2  49152
#define OFF_WJ 65536
#define OFF_YI 66048
#define OFF_WI 66560
#define OFF_YJ 67072
#define SMEM_BYTES (67584 + 256)

__global__ __launch_bounds__(256, 2)
void svm_quad_mma_kernel(const float* __restrict__ y,
                         const int* __restrict__ coeff_p,
                         const int* __restrict__ degree_p) {
    extern __shared__ char smem_raw[];
    const uint32_t raw = smem_u32(smem_raw);
    const uint32_t base = (raw + 127u) & ~127u;
    char* smem = smem_raw + (base - raw);

    const int tid = threadIdx.x;
    const int wid = tid >> 5;
    const int lid = tid & 31;
    const int wm  = wid & 3;   // 4 warps along M
    const int wn  = wid >> 2;  // 2 warps along N

    // ---- triangular decode: blockIdx.x -> (I, J), I <= J ----
    int idx = blockIdx.x;
    int I = (int)((2.0 * NTILES + 1.0
                   - sqrt((2.0 * NTILES + 1.0) * (2.0 * NTILES + 1.0) - 8.0 * idx)) * 0.5);
    if (I > NTILES - 1) I = NTILES - 1;
    if (I < 0) I = 0;
    #pragma unroll 1
    while (I > 0 && (I * NTILES - (I * (I - 1)) / 2) > idx) --I;
    #pragma unroll 1
    while (((I + 1) * NTILES - ((I + 1) * I) / 2) <= idx) ++I;
    const int J = I + (idx - (I * NTILES - (I * (I - 1)) / 2));
    const int bi = I * BLK;
    const int bj = J * BLK;
    const bool offdiag = (I != J);

    // ---- async tile loads (4 x 1024 x 16B chunks, swizzled) ----
    {
        const char* sHiA = (const char*)(g_hi + (size_t)bi * DD);
        const char* sHiB = (const char*)(g_hi + (size_t)bj * DD);
        const char* sC1  = (const char*)(g_c1 + (size_t)bi * 128);
        const char* sC2  = (const char*)(g_c2 + (size_t)bj * 128);
        #pragma unroll
        for (int it = 0; it < 4; ++it) {
            int i = tid + it * 256;        // 0..1023 = row*8 + c16
            int row = i >> 3, c16 = i & 7;
            int sw = row * 128 + ((c16 ^ (row & 7)) << 4);
            int lin = i * 16;
            CP_ASYNC16(base + T_HIA + sw, sHiA + lin);
            CP_ASYNC16(base + T_HIB + sw, sHiB + lin);
            CP_ASYNC16(base + T_C1  + sw, sC1  + lin);
            CP_ASYNC16(base + T_C2  + sw, sC2  + lin);
        }
        CP_COMMIT();
        if (tid < 128) {
            *(float*)(smem + OFF_WJ + tid * 4) = g_w[bj + tid];
            *(float*)(smem + OFF_YI + tid * 4) = y[bi + tid];
            *(float*)(smem + OFF_WI + tid * 4) = g_w[bi + tid];
            *(float*)(smem + OFF_YJ + tid * 4) = y[bj + tid];
        }
        CP_WAIT0();
    }
    __syncthreads();

    float acc[2][8][4];
    #pragma unroll
    for (int am = 0; am < 2; ++am)
        #pragma unroll
        for (int bn = 0; bn < 8; ++bn)
            #pragma unroll
            for (int r = 0; r < 4; ++r) acc[am][bn][r] = 0.f;

    // ======== pass 1: bf16 hi*hi, K=64 (4 ks of 16) ========
    {
        const int q   = lid >> 3;
        const int seg = lid & 7;
        const int rowA0 = wm * 32 + seg + ((q & 1) << 3);
        const int chA   = q >> 1;
        const int rowB0 = wn * 64 + seg + ((q >> 1) << 3);
        const int chB   = q & 1;
        const uint32_t aB = base + T_HIA;
        const uint32_t bB = base + T_HIB;
        #pragma unroll
        for (int ks = 0; ks < 4; ++ks) {
            uint32_t af[2][4];
            #pragma unroll
            for (int am = 0; am < 2; ++am) {
                int row = rowA0 + am * 16;
                int ch  = (chA + 2 * ks) ^ (row & 7);
                ldsm_x4(af[am][0], af[am][1], af[am][2], af[am][3],
                        aB + row * 128 + (ch << 4));
            }
            uint32_t bf[8][2];
            #pragma unroll
            for (int bn2 = 0; bn2 < 4; ++bn2) {
                int row = rowB0 + bn2 * 16;
                int ch  = (chB + 2 * ks) ^ (row & 7);
                ldsm_x4(bf[bn2 * 2][0], bf[bn2 * 2][1],
                        bf[bn2 * 2 + 1][0], bf[bn2 * 2 + 1][1],
                        bB + row * 128 + (ch << 4));
            }
            #pragma unroll
            for (int am = 0; am < 2; ++am)
                #pragma unroll
                for (int bn = 0; bn < 8; ++bn)
                    mma_16816(acc[am][bn], af[am], bf[bn]);
        }
    }

    // ======== pass 2: e4m3 cross terms, K=128 fp8 (4 ksteps of 32) ========
    // A-frag lanes: row = rowbase + ((lid>>3)&1)*8 + (lid&7), chunk = 2s + (lid>>4)
    // B-frag lanes: nrow = nbase + ((lid>>4)&1)*8 + (lid&7), chunk = 2s + ((lid>>3)&1)
    {
        const int segA = ((lid >> 3) & 1) * 8 + (lid & 7);
        const int dchA = (lid >> 4);
        const int segB = ((lid >> 4) & 1) * 8 + (lid & 7);
        const int dchB = ((lid >> 3) & 1);
        const uint32_t aB = base + T_C1;
        const uint32_t bB = base + T_C2;
        #pragma unroll
        for (int s = 0; s < 4; ++s) {
            uint32_t af[2][4];
            #pragma unroll
            for (int am = 0; am < 2; ++am) {
                int row = wm * 32 + am * 16 + segA;
                int ch  = (2 * s + dchA) ^ (row & 7);
                ldsm_x4(af[am][0], af[am][1], af[am][2], af[am][3],
                        aB + row * 128 + (ch << 4));
            }
            uint32_t bf[8][2];
            #pragma unroll
            for (int j = 0; j < 4; ++j) {
                int nrow = wn * 64 + j * 16 + segB;
                int ch   = (2 * s + dchB) ^ (nrow & 7);
                ldsm_x4(bf[2 * j][0], bf[2 * j][1],
                        bf[2 * j + 1][0], bf[2 * j + 1][1],
                        bB + nrow * 128 + (ch << 4));
            }
            #pragma unroll
            for (int am = 0; am < 2; ++am)
                #pragma unroll
                for (int bn = 0; bn < 8; ++bn)
                    mma_fp8(acc[am][bn], af[am], bf[bn]);
        }
    }

    // ---- epilogue: k = (v+coeff)^deg; off-diag tiles count both triangles ----
    const float coeff = scal_as_float(coeff_p);
    const int   deg   = scal_as_int(degree_p);
    const float* s_wJ = (const float*)(smem + OFF_WJ);
    const float* s_yI = (const float*)(smem + OFF_YI);
    const float* s_wI = (const float*)(smem + OFF_WI);
    const float* s_yJ = (const float*)(smem + OFF_YJ);

    const int rBase = wm * 32 + (lid >> 2);
    const int cBase = wn * 64 + 2 * (lid & 3);

    float part = 0.f;
    #pragma unroll
    for (int am = 0; am < 2; ++am) {
        const int r0i = rBase + am * 16;
        const float yr0 = s_yI[r0i],     yr1 = s_yI[r0i + 8];
        const float wr0 = s_wI[r0i],     wr1 = s_wI[r0i + 8];
        float s0w = 0.f, s1w = 0.f;
        float s0y = 0.f, s1y = 0.f;
        #pragma unroll
        for (int bn = 0; bn < 8; ++bn) {
            const int c0i = cBase + bn * 8;
            const float wc0 = s_wJ[c0i], wc1 = s_wJ[c0i + 1];
            const float yc0 = s_yJ[c0i], yc1 = s_yJ[c0i + 1];
            float k0, k1, k2, k3;
            if (deg == 3) {
                float v0 = acc[am][bn][0] + coeff;
                float v1 = acc[am][bn][1] + coeff;
                float v2 = acc[am][bn][2] + coeff;
                float v3 = acc[am][bn][3] + coeff;
                k0 = v0 * v0 * v0; k1 = v1 * v1 * v1;
                k2 = v2 * v2 * v2; k3 = v3 * v3 * v3;
            } else {
                float v[4], kk[4];
                #pragma unroll
                for (int r = 0; r < 4; ++r) {
                    v[r] = acc[am][bn][r] + coeff;
                    float p = 1.f;
                    for (int d = 0; d < deg; ++d) p *= v[r];
                    kk[r] = p;
                }
                k0 = kk[0]; k1 = kk[1]; k2 = kk[2]; k3 = kk[3];
            }
            s0w = fmaf(wc0, k0, s0w); s0w = fmaf(wc1, k1, s0w);
            s1w = fmaf(wc0, k2, s1w); s1w = fmaf(wc1, k3, s1w);
            s0y = fmaf(yc0, k0, s0y); s0y = fmaf(yc1, k1, s0y);
            s1y = fmaf(yc0, k2, s1y); s1y = fmaf(yc1, k3, s1y);
        }
        part = fmaf(yr0, s0w, part);
        part = fmaf(yr1, s1w, part);
        if (offdiag) {
            part = fmaf(wr0, s0y, part);
            part = fmaf(wr1, s1y, part);
        }
    }

    // ---- block reduce -> per-CTA partial ----
    #pragma unroll
    for (int o = 16; o > 0; o >>= 1)
        part += __shfl_down_sync(0xffffffffu, part, o);
    __shared__ float red[8];
    if (lid == 0) red[wid] = part;
    __syncthreads();
    if (tid == 0) {
        float s = 0.f;
        #pragma unroll
        for (int w = 0; w < 8; ++w) s += red[w];
        g_part[blockIdx.x] = s;
    }
}

// ---------------- final reduction + loss ----------------
__global__ __launch_bounds__(256)
void svm_fin_kernel(const float* __restrict__ b,
                    const int*   __restrict__ C_p,
                    const int*   __restrict__ lambd_p,
                    float* __restrict__ out) {
    const int tid = threadIdx.x;
    double q = 0.0;
    for (int i = tid; i < NPAIRS; i += 256) q += (double)g_part[i];
    double sa = 0.0, sx = 0.0, sy = 0.0;
    for (int i = tid; i < PREP_BLOCKS; i += 256) {
        sa += (double)g_pSa[i];
        sx += (double)g_pSxi[i];
        sy += (double)g_pSy[i];
    }
    #pragma unroll
    for (int o = 16; o > 0; o >>= 1) {
        q  += __shfl_down_sync(0xffffffffu, q,  o);
        sa += __shfl_down_sync(0xffffffffu, sa, o);
        sx += __shfl_down_sync(0xffffffffu, sx, o);
        sy += __shfl_down_sync(0xffffffffu, sy, o);
    }
    __shared__ double rq[8], ra[8], rx[8], ry[8];
    int wid = tid >> 5, lid = tid & 31;
    if (lid == 0) { rq[wid] = q; ra[wid] = sa; rx[wid] = sx; ry[wid] = sy; }
    __syncthreads();
    if (tid == 0) {
        double Q = 0, Sa = 0, Sxi = 0, Sy = 0;
        #pragma unroll
        for (int w = 0; w < 8; ++w) {
            Q += rq[w]; Sa += ra[w]; Sxi += rx[w]; Sy += ry[w];
        }
        double C  = (double)scal_as_float(C_p);
        double la = (double)scal_as_float(lambd_p);
        double loss = 0.5 * Sa + C * Sxi
                    + la * ((Q + (double)b[0] * Sy + Sxi) / (double)NN - 1.0);
        out[0] = (float)loss;
    }
}

// ---------------- launch ----------------
extern "C" void kernel_launch(void* const* d_in, const int* in_sizes, int n_in,
                              void* d_out, int out_size) {
    const float* x      = (const float*)d_in[0];
    const float* y      = (const float*)d_in[1];
    const float* alpha  = (const float*)d_in[2];
    const float* xi     = (const float*)d_in[3];
    const float* b      = (const float*)d_in[4];
    const int*   coeff  = (const int*)d_in[5];
    const int*   degree = (const int*)d_in[6];
    const int*   Cc     = (const int*)d_in[7];
    const int*   lambd  = (const int*)d_in[8];
    float* out = (float*)d_out;

    static bool attr_set = false;
    if (!attr_set) {
        cudaFuncSetAttribute(svm_quad_mma_kernel,
                             cudaFuncAttributeMaxDynamicSharedMemorySize, SMEM_BYTES);
        attr_set = true;
    }

    svm_prep_kernel<<<PREP_BLOCKS, 256>>>(x, alpha, xi, y);
    svm_quad_mma_kernel<<<NPAIRS, 256, SMEM_BYTES>>>(y, coeff, degree);
    svm_fin_kernel<<<1, 256>>>(b, Cc, lambd, out);
}